// round 3
// baseline (speedup 1.0000x reference)
#include <cuda_runtime.h>
#include <cstdint>

// Problem constants
#define N_NODES 50000
#define N_EDGES 800000
#define FEAT    256
#define N_RELS  8
#define SQRT_HALF 0.70710678118654752f

// ---------------- scratch (device globals; no runtime allocation) -----------
__device__ float    g_hx[(size_t)N_RELS * N_NODES * FEAT];  // 409.6 MB
__device__ int      g_counts[N_NODES];
__device__ int      g_offsets[N_NODES + 1];
__device__ int      g_cursor[N_NODES];
__device__ unsigned g_sorted[N_EDGES];   // packed: src | (rel<<20)

// ---------------- kernel 1: zero counts ------------------------------------
__global__ void k_zero_counts() {
    int i = blockIdx.x * blockDim.x + threadIdx.x;
    if (i < N_NODES) g_counts[i] = 0;
}

// ---------------- kernel 2: histogram over dst ------------------------------
// edge_index is int32 (JAX x64 disabled downcasts int64 -> int32)
__global__ void k_hist(const int* __restrict__ edge_index) {
    int e = blockIdx.x * blockDim.x + threadIdx.x;
    if (e < N_EDGES) {
        int d = edge_index[N_EDGES + e];  // dst row
        if (d >= 0 && d < N_NODES) atomicAdd(&g_counts[d], 1);
    }
}

// ---------------- kernel 3: single-block exclusive scan ----------------------
// 1024 threads, 49 items each (1024*49 = 50176 >= 50000)
__global__ void k_scan() {
    __shared__ int s[1024];
    const int ITEMS = 49;
    int t = threadIdx.x;
    int base = t * ITEMS;
    int sum = 0;
    for (int i = 0; i < ITEMS; i++) {
        int idx = base + i;
        if (idx < N_NODES) sum += g_counts[idx];
    }
    s[t] = sum;
    __syncthreads();
    int val = sum;
    for (int off = 1; off < 1024; off <<= 1) {
        int v = (t >= off) ? s[t - off] : 0;
        __syncthreads();
        val += v;
        s[t] = val;
        __syncthreads();
    }
    int run = val - sum;  // exclusive prefix of this thread's chunk
    for (int i = 0; i < ITEMS; i++) {
        int idx = base + i;
        if (idx < N_NODES) {
            g_offsets[idx] = run;
            g_cursor[idx]  = run;
            run += g_counts[idx];
        }
    }
    if (t == 0) g_offsets[N_NODES] = N_EDGES;
}

// ---------------- kernel 4: scatter edges into dst-sorted order --------------
__global__ void k_scatter(const int* __restrict__ edge_index,
                          const int* __restrict__ edge_type) {
    int e = blockIdx.x * blockDim.x + threadIdx.x;
    if (e < N_EDGES) {
        int s = edge_index[e];
        int d = edge_index[N_EDGES + e];
        int r = edge_type[e];
        if (d >= 0 && d < N_NODES) {
            int pos = atomicAdd(&g_cursor[d], 1);
            g_sorted[pos] = (unsigned)s | ((unsigned)r << 20);
        }
    }
}

// ---------------- kernel 5: batched GEMM -------------------------------------
// z = 0..7 : g_hx[z] = x @ weight[z]
// z = 8    : out     = h_bias + sqrt(0.5) * (x @ loop_weight)
#define BM 128
#define BN 64
#define BK 16
__global__ __launch_bounds__(256) void k_gemm(
    const float* __restrict__ x,
    const float* __restrict__ weight,
    const float* __restrict__ loop_weight,
    const float* __restrict__ h_bias,
    float* __restrict__ out)
{
    __shared__ float As[BK][BM];
    __shared__ float Bs[BK][BN];

    const int r  = blockIdx.z;
    const float* W = (r < N_RELS) ? (weight + (size_t)r * FEAT * FEAT) : loop_weight;
    const int m0 = blockIdx.x * BM;
    const int n0 = blockIdx.y * BN;
    const int tid  = threadIdx.x;
    const int trow = tid >> 4;   // 0..15 -> 8 rows each
    const int tcol = tid & 15;   // 0..15 -> 4 cols each

    float acc[8][4];
    #pragma unroll
    for (int i = 0; i < 8; i++)
        #pragma unroll
        for (int j = 0; j < 4; j++) acc[i][j] = 0.f;

    for (int k0 = 0; k0 < FEAT; k0 += BK) {
        // load X tile 128x16 (512 float4, 2 per thread), transpose into As[k][m]
        #pragma unroll
        for (int j = 0; j < 2; j++) {
            int idx = tid + j * 256;
            int row = idx >> 2;      // 0..127
            int kv  = idx & 3;       // float4 index along k
            int gm  = m0 + row;
            float4 v = make_float4(0.f, 0.f, 0.f, 0.f);
            if (gm < N_NODES)
                v = *(const float4*)(x + (size_t)gm * FEAT + k0 + kv * 4);
            As[kv * 4 + 0][row] = v.x;
            As[kv * 4 + 1][row] = v.y;
            As[kv * 4 + 2][row] = v.z;
            As[kv * 4 + 3][row] = v.w;
        }
        // load W tile 16x64 (256 float4, 1 per thread)
        {
            int row = tid >> 4;   // 0..15
            int nv  = tid & 15;   // 0..15
            float4 v = *(const float4*)(W + (size_t)(k0 + row) * FEAT + n0 + nv * 4);
            *(float4*)&Bs[row][nv * 4] = v;
        }
        __syncthreads();

        #pragma unroll
        for (int k = 0; k < BK; k++) {
            float a[8], b[4];
            *(float4*)&a[0] = *(const float4*)&As[k][trow * 8];
            *(float4*)&a[4] = *(const float4*)&As[k][trow * 8 + 4];
            *(float4*)&b[0] = *(const float4*)&Bs[k][tcol * 4];
            #pragma unroll
            for (int i = 0; i < 8; i++)
                #pragma unroll
                for (int j = 0; j < 4; j++)
                    acc[i][j] += a[i] * b[j];
        }
        __syncthreads();
    }

    const int gn = n0 + tcol * 4;
    #pragma unroll
    for (int i = 0; i < 8; i++) {
        int gm = m0 + trow * 8 + i;
        if (gm >= N_NODES) break;
        if (r < N_RELS) {
            float4 v = make_float4(acc[i][0], acc[i][1], acc[i][2], acc[i][3]);
            *(float4*)(g_hx + (((size_t)r * N_NODES + gm) << 8) + gn) = v;
        } else {
            float4 bv = *(const float4*)(h_bias + gn);
            float4 v = make_float4(bv.x + SQRT_HALF * acc[i][0],
                                   bv.y + SQRT_HALF * acc[i][1],
                                   bv.z + SQRT_HALF * acc[i][2],
                                   bv.w + SQRT_HALF * acc[i][3]);
            *(float4*)(out + ((size_t)gm << 8) + gn) = v;
        }
    }
}

// ---------------- kernel 6: per-node aggregation (1 warp / node) -------------
__global__ __launch_bounds__(256) void k_agg(float* __restrict__ out) {
    int node = blockIdx.x * blockDim.y + threadIdx.y;
    if (node >= N_NODES) return;
    int lane = threadIdx.x;
    int beg = g_offsets[node];
    int end = g_offsets[node + 1];

    float4 a0 = make_float4(0.f, 0.f, 0.f, 0.f);
    float4 a1 = make_float4(0.f, 0.f, 0.f, 0.f);

    for (int i = beg; i < end; i++) {
        unsigned p = g_sorted[i];
        unsigned src = p & 0xFFFFFu;
        unsigned rel = p >> 20;
        const float4* row = (const float4*)(g_hx + (((size_t)rel * N_NODES + src) << 8));
        float4 v0 = __ldg(&row[lane]);        // cols [4*lane, 4*lane+4)
        float4 v1 = __ldg(&row[lane + 32]);   // cols [128+4*lane, ...)
        a0.x += v0.x; a0.y += v0.y; a0.z += v0.z; a0.w += v0.w;
        a1.x += v1.x; a1.y += v1.y; a1.z += v1.z; a1.w += v1.w;
    }

    float4* o = (float4*)(out + ((size_t)node << 8));
    float4 c0 = o[lane];
    float4 c1 = o[lane + 32];
    c0.x += SQRT_HALF * a0.x; c0.y += SQRT_HALF * a0.y;
    c0.z += SQRT_HALF * a0.z; c0.w += SQRT_HALF * a0.w;
    c1.x += SQRT_HALF * a1.x; c1.y += SQRT_HALF * a1.y;
    c1.z += SQRT_HALF * a1.z; c1.w += SQRT_HALF * a1.w;
    o[lane]      = c0;
    o[lane + 32] = c1;
}

// ---------------- launch -----------------------------------------------------
extern "C" void kernel_launch(void* const* d_in, const int* in_sizes, int n_in,
                              void* d_out, int out_size) {
    const int*   edge_index  = (const int*)d_in[0];
    const float* x           = (const float*)d_in[1];
    const int*   edge_type   = (const int*)d_in[2];
    const float* weight      = (const float*)d_in[3];
    const float* h_bias      = (const float*)d_in[4];
    const float* loop_weight = (const float*)d_in[5];
    float* out = (float*)d_out;

    // sorting pipeline
    k_zero_counts<<<(N_NODES + 255) / 256, 256>>>();
    k_hist<<<(N_EDGES + 255) / 256, 256>>>(edge_index);
    k_scan<<<1, 1024>>>();
    k_scatter<<<(N_EDGES + 255) / 256, 256>>>(edge_index, edge_type);

    // batched GEMM: 8 relations + self-loop
    dim3 gg((N_NODES + BM - 1) / BM, FEAT / BN, N_RELS + 1);
    k_gemm<<<gg, 256>>>(x, weight, loop_weight, h_bias, out);

    // per-node aggregation
    dim3 bb(32, 8);
    k_agg<<<(N_NODES + 7) / 8, bb>>>(out);
}

// round 5
// speedup vs baseline: 1.4518x; 1.4518x over previous
#include <cuda_runtime.h>
#include <cstdint>

// Problem constants
#define N_NODES 50000
#define N_EDGES 800000
#define FEAT    256
#define N_RELS  8
#define SQRT_HALF 0.70710678118654752f

// ---------------- scratch (device globals; no runtime allocation) -----------
__device__ float    g_hx[(size_t)N_RELS * N_NODES * FEAT];  // 409.6 MB
__device__ int      g_counts[N_NODES];
__device__ int      g_offsets[N_NODES + 1];
__device__ int      g_cursor[N_NODES];
__device__ unsigned g_sorted[N_EDGES];   // packed: src | (rel<<20)

// ---------------- kernel 1: zero counts ------------------------------------
__global__ void k_zero_counts() {
    int i = blockIdx.x * blockDim.x + threadIdx.x;
    if (i < N_NODES) g_counts[i] = 0;
}

// ---------------- kernel 2: histogram over dst ------------------------------
__global__ void k_hist(const int* __restrict__ edge_index) {
    int e = blockIdx.x * blockDim.x + threadIdx.x;
    if (e < N_EDGES) {
        int d = edge_index[N_EDGES + e];  // dst row
        if (d >= 0 && d < N_NODES) atomicAdd(&g_counts[d], 1);
    }
}

// ---------------- kernel 3: single-block exclusive scan ----------------------
__global__ void k_scan() {
    __shared__ int s[1024];
    const int ITEMS = 49;
    int t = threadIdx.x;
    int base = t * ITEMS;
    int sum = 0;
    for (int i = 0; i < ITEMS; i++) {
        int idx = base + i;
        if (idx < N_NODES) sum += g_counts[idx];
    }
    s[t] = sum;
    __syncthreads();
    int val = sum;
    for (int off = 1; off < 1024; off <<= 1) {
        int v = (t >= off) ? s[t - off] : 0;
        __syncthreads();
        val += v;
        s[t] = val;
        __syncthreads();
    }
    int run = val - sum;
    for (int i = 0; i < ITEMS; i++) {
        int idx = base + i;
        if (idx < N_NODES) {
            g_offsets[idx] = run;
            g_cursor[idx]  = run;
            run += g_counts[idx];
        }
    }
    if (t == 0) g_offsets[N_NODES] = N_EDGES;
}

// ---------------- kernel 4: scatter edges into dst-sorted order --------------
__global__ void k_scatter(const int* __restrict__ edge_index,
                          const int* __restrict__ edge_type) {
    int e = blockIdx.x * blockDim.x + threadIdx.x;
    if (e < N_EDGES) {
        int s = edge_index[e];
        int d = edge_index[N_EDGES + e];
        int r = edge_type[e];
        if (d >= 0 && d < N_NODES) {
            int pos = atomicAdd(&g_cursor[d], 1);
            g_sorted[pos] = (unsigned)s | ((unsigned)r << 20);
        }
    }
}

// ---------------- helpers: tf32 convert + mma ---------------------------------
__device__ __forceinline__ unsigned f2tf(float f) {
    unsigned r;
    asm("cvt.rna.tf32.f32 %0, %1;" : "=r"(r) : "f"(f));
    return r;
}

__device__ __forceinline__ void mma_tf32(float c[4], const unsigned a[4], const unsigned b[2]) {
    asm volatile(
        "mma.sync.aligned.m16n8k8.row.col.f32.tf32.tf32.f32 "
        "{%0,%1,%2,%3},{%4,%5,%6,%7},{%8,%9},{%0,%1,%2,%3};"
        : "+f"(c[0]), "+f"(c[1]), "+f"(c[2]), "+f"(c[3])
        : "r"(a[0]), "r"(a[1]), "r"(a[2]), "r"(a[3]), "r"(b[0]), "r"(b[1]));
}

// ---------------- kernel 5: batched tf32 tensor-core GEMM ---------------------
// z = 0..7 : g_hx[z] = x @ weight[z]
// z = 8    : out     = h_bias + sqrt(0.5) * (x @ loop_weight)
#define BM 128
#define BN 64
#define BK 32
#define APAD 5   // As row pitch = BM + APAD = 133
#define BPAD 4   // Bs row pitch = BN + BPAD = 68

__global__ __launch_bounds__(256) void k_gemm_tc(
    const float* __restrict__ x,
    const float* __restrict__ weight,
    const float* __restrict__ loop_weight,
    const float* __restrict__ h_bias,
    float* __restrict__ out)
{
    __shared__ unsigned As[BK][BM + APAD];  // tf32, [k][m]
    __shared__ unsigned Bs[BK][BN + BPAD];  // tf32, [k][n]

    const int r  = blockIdx.z;
    const float* W = (r < N_RELS) ? (weight + (size_t)r * FEAT * FEAT) : loop_weight;
    const int m0 = blockIdx.x * BM;
    const int n0 = blockIdx.y * BN;

    const int tid  = threadIdx.x;
    const int lane = tid & 31;
    const int warp = tid >> 5;
    const int wm   = warp & 3;        // 0..3 -> 32-row slice
    const int wn   = warp >> 2;       // 0..1 -> 32-col slice
    const int g    = lane >> 2;       // group id (0..7)
    const int tig  = lane & 3;        // thread-in-group (0..3)

    float c[2][4][4];                 // [mfrag][nfrag][reg]
    #pragma unroll
    for (int i = 0; i < 2; i++)
        #pragma unroll
        for (int j = 0; j < 4; j++)
            #pragma unroll
            for (int q = 0; q < 4; q++) c[i][j][q] = 0.f;

    // A-load mapping: 2 threads per row, 16 contiguous k each
    const int a_row   = tid >> 1;           // 0..127
    const int a_khalf = (tid & 1) * 16;     // 0 or 16
    // B-load mapping: 8 threads per row, 8 contiguous n each
    const int b_row  = tid >> 3;            // 0..31
    const int b_ncol = (tid & 7) * 8;       // 0..56

    for (int k0 = 0; k0 < FEAT; k0 += BK) {
        // ---- stage A tile (128 x 32), transposed into As[k][m], tf32 ----
        {
            int gm = m0 + a_row;
            float f[16];
            if (gm < N_NODES) {
                const float* p = x + (size_t)gm * FEAT + k0 + a_khalf;
                #pragma unroll
                for (int i = 0; i < 4; i++) {
                    float4 v = *(const float4*)(p + i * 4);
                    f[i * 4 + 0] = v.x; f[i * 4 + 1] = v.y;
                    f[i * 4 + 2] = v.z; f[i * 4 + 3] = v.w;
                }
            } else {
                #pragma unroll
                for (int i = 0; i < 16; i++) f[i] = 0.f;
            }
            #pragma unroll
            for (int i = 0; i < 16; i++)
                As[a_khalf + i][a_row] = f2tf(f[i]);
        }
        // ---- stage B tile (32 x 64) into Bs[k][n], tf32 ----
        {
            const float* p = W + (size_t)(k0 + b_row) * FEAT + n0 + b_ncol;
            #pragma unroll
            for (int i = 0; i < 2; i++) {
                float4 v = *(const float4*)(p + i * 4);
                unsigned* q = &Bs[b_row][b_ncol + i * 4];
                q[0] = f2tf(v.x); q[1] = f2tf(v.y);
                q[2] = f2tf(v.z); q[3] = f2tf(v.w);
            }
        }
        __syncthreads();

        // ---- mma over 4 k8-steps ----
        #pragma unroll
        for (int k8 = 0; k8 < BK; k8 += 8) {
            unsigned a[2][4], b[4][2];
            #pragma unroll
            for (int mf = 0; mf < 2; mf++) {
                int m = wm * 32 + mf * 16;
                a[mf][0] = As[k8 + tig    ][m + g    ];
                a[mf][1] = As[k8 + tig    ][m + g + 8];
                a[mf][2] = As[k8 + tig + 4][m + g    ];
                a[mf][3] = As[k8 + tig + 4][m + g + 8];
            }
            #pragma unroll
            for (int nf = 0; nf < 4; nf++) {
                int n = wn * 32 + nf * 8;
                b[nf][0] = Bs[k8 + tig    ][n + g];
                b[nf][1] = Bs[k8 + tig + 4][n + g];
            }
            #pragma unroll
            for (int mf = 0; mf < 2; mf++)
                #pragma unroll
                for (int nf = 0; nf < 4; nf++)
                    mma_tf32(c[mf][nf], a[mf], b[nf]);
        }
        __syncthreads();
    }

    // ---- epilogue ----
    #pragma unroll
    for (int mf = 0; mf < 2; mf++) {
        int row0 = m0 + wm * 32 + mf * 16 + g;   // rows row0, row0+8
        #pragma unroll
        for (int nf = 0; nf < 4; nf++) {
            int col = n0 + wn * 32 + nf * 8 + 2 * tig;
            if (r < N_RELS) {
                if (row0 < N_NODES)
                    *(float2*)(g_hx + (((size_t)r * N_NODES + row0) << 8) + col) =
                        make_float2(c[mf][nf][0], c[mf][nf][1]);
                if (row0 + 8 < N_NODES)
                    *(float2*)(g_hx + (((size_t)r * N_NODES + row0 + 8) << 8) + col) =
                        make_float2(c[mf][nf][2], c[mf][nf][3]);
            } else {
                float2 bv = *(const float2*)(h_bias + col);
                if (row0 < N_NODES)
                    *(float2*)(out + ((size_t)row0 << 8) + col) =
                        make_float2(bv.x + SQRT_HALF * c[mf][nf][0],
                                    bv.y + SQRT_HALF * c[mf][nf][1]);
                if (row0 + 8 < N_NODES)
                    *(float2*)(out + ((size_t)(row0 + 8) << 8) + col) =
                        make_float2(bv.x + SQRT_HALF * c[mf][nf][2],
                                    bv.y + SQRT_HALF * c[mf][nf][3]);
            }
        }
    }
}

// ---------------- kernel 6: per-node aggregation (1 warp / node) -------------
__global__ __launch_bounds__(256) void k_agg(float* __restrict__ out) {
    int node = blockIdx.x * blockDim.y + threadIdx.y;
    if (node >= N_NODES) return;
    int lane = threadIdx.x;
    int beg = g_offsets[node];
    int end = g_offsets[node + 1];

    float4 a0 = make_float4(0.f, 0.f, 0.f, 0.f);
    float4 a1 = make_float4(0.f, 0.f, 0.f, 0.f);

    for (int i = beg; i < end; i++) {
        unsigned p = g_sorted[i];
        unsigned src = p & 0xFFFFFu;
        unsigned rel = p >> 20;
        const float4* row = (const float4*)(g_hx + (((size_t)rel * N_NODES + src) << 8));
        float4 v0 = __ldg(&row[lane]);
        float4 v1 = __ldg(&row[lane + 32]);
        a0.x += v0.x; a0.y += v0.y; a0.z += v0.z; a0.w += v0.w;
        a1.x += v1.x; a1.y += v1.y; a1.z += v1.z; a1.w += v1.w;
    }

    float4* o = (float4*)(out + ((size_t)node << 8));
    float4 c0 = o[lane];
    float4 c1 = o[lane + 32];
    c0.x += SQRT_HALF * a0.x; c0.y += SQRT_HALF * a0.y;
    c0.z += SQRT_HALF * a0.z; c0.w += SQRT_HALF * a0.w;
    c1.x += SQRT_HALF * a1.x; c1.y += SQRT_HALF * a1.y;
    c1.z += SQRT_HALF * a1.z; c1.w += SQRT_HALF * a1.w;
    o[lane]      = c0;
    o[lane + 32] = c1;
}

// ---------------- launch -----------------------------------------------------
extern "C" void kernel_launch(void* const* d_in, const int* in_sizes, int n_in,
                              void* d_out, int out_size) {
    const int*   edge_index  = (const int*)d_in[0];
    const float* x           = (const float*)d_in[1];
    const int*   edge_type   = (const int*)d_in[2];
    const float* weight      = (const float*)d_in[3];
    const float* h_bias      = (const float*)d_in[4];
    const float* loop_weight = (const float*)d_in[5];
    float* out = (float*)d_out;

    // sorting pipeline
    k_zero_counts<<<(N_NODES + 255) / 256, 256>>>();
    k_hist<<<(N_EDGES + 255) / 256, 256>>>(edge_index);
    k_scan<<<1, 1024>>>();
    k_scatter<<<(N_EDGES + 255) / 256, 256>>>(edge_index, edge_type);

    // batched tf32 GEMM: 8 relations + self-loop
    dim3 gg((N_NODES + BM - 1) / BM, FEAT / BN, N_RELS + 1);
    k_gemm_tc<<<gg, 256>>>(x, weight, loop_weight, h_bias, out);

    // per-node aggregation
    dim3 bb(32, 8);
    k_agg<<<(N_NODES + 7) / 8, bb>>>(out);
}

// round 6
// speedup vs baseline: 3.5221x; 2.4261x over previous
#include <cuda_runtime.h>
#include <cuda_fp16.h>
#include <cstdint>

#define N_NODES 50000
#define N_EDGES 800000
#define FEAT    256
#define N_RELS  8
#define SQRT_HALF 0.70710678118654752f

// ---------------- scratch ----------------------------------------------------
__device__ __half g_hxh[(size_t)N_RELS * N_NODES * FEAT];   // 204.8 MB fp16
__device__ __half g_xh[(size_t)N_NODES * FEAT];             // 25.6 MB fp16
__device__ __half g_wt[(size_t)(N_RELS + 1) * FEAT * FEAT]; // W^T fp16, [r][n][k]
__device__ int      g_counts[N_NODES];
__device__ int      g_offsets[N_NODES + 1];
__device__ int      g_cursor[N_NODES];
__device__ unsigned g_sorted[N_EDGES];   // packed: src | (rel<<20)

// ---------------- sort pipeline ----------------------------------------------
__global__ void k_zero_counts() {
    int i = blockIdx.x * blockDim.x + threadIdx.x;
    if (i < N_NODES) g_counts[i] = 0;
}

__global__ void k_hist(const int* __restrict__ edge_index) {
    int e = blockIdx.x * blockDim.x + threadIdx.x;
    if (e < N_EDGES) {
        int d = edge_index[N_EDGES + e];
        if (d >= 0 && d < N_NODES) atomicAdd(&g_counts[d], 1);
    }
}

__global__ void k_scan() {
    __shared__ int s[1024];
    const int ITEMS = 49;
    int t = threadIdx.x;
    int base = t * ITEMS;
    int sum = 0;
    for (int i = 0; i < ITEMS; i++) {
        int idx = base + i;
        if (idx < N_NODES) sum += g_counts[idx];
    }
    s[t] = sum;
    __syncthreads();
    int val = sum;
    for (int off = 1; off < 1024; off <<= 1) {
        int v = (t >= off) ? s[t - off] : 0;
        __syncthreads();
        val += v;
        s[t] = val;
        __syncthreads();
    }
    int run = val - sum;
    for (int i = 0; i < ITEMS; i++) {
        int idx = base + i;
        if (idx < N_NODES) {
            g_offsets[idx] = run;
            g_cursor[idx]  = run;
            run += g_counts[idx];
        }
    }
    if (t == 0) g_offsets[N_NODES] = N_EDGES;
}

__global__ void k_scatter(const int* __restrict__ edge_index,
                          const int* __restrict__ edge_type) {
    int e = blockIdx.x * blockDim.x + threadIdx.x;
    if (e < N_EDGES) {
        int s = edge_index[e];
        int d = edge_index[N_EDGES + e];
        int r = edge_type[e];
        if (d >= 0 && d < N_NODES) {
            int pos = atomicAdd(&g_cursor[d], 1);
            g_sorted[pos] = (unsigned)s | ((unsigned)r << 20);
        }
    }
}

// ---------------- converts ---------------------------------------------------
// x fp32 -> fp16 (row-major, same layout)
__global__ void k_convert_x(const float* __restrict__ x) {
    int i = blockIdx.x * blockDim.x + threadIdx.x;   // float2 index
    const int total = N_NODES * FEAT / 2;
    if (i < total) {
        float2 v = *((const float2*)x + i);
        *((__half2*)g_xh + i) = __floats2half2_rn(v.x, v.y);
    }
}

// W[r][k][n] fp32 -> g_wt[r][n][k] fp16 (transpose, 32x32 smem tiles)
__global__ void k_convert_w(const float* __restrict__ W, const float* __restrict__ LW) {
    int r = blockIdx.z;
    const float* src = (r < N_RELS) ? (W + (size_t)r * FEAT * FEAT) : LW;
    int k0 = blockIdx.x * 32, n0 = blockIdx.y * 32;
    __shared__ float t[32][33];
    for (int i = threadIdx.y; i < 32; i += 8)
        t[i][threadIdx.x] = src[(size_t)(k0 + i) * FEAT + n0 + threadIdx.x];
    __syncthreads();
    for (int i = threadIdx.y; i < 32; i += 8)
        g_wt[((size_t)r << 16) + (size_t)(n0 + i) * FEAT + k0 + threadIdx.x] =
            __float2half(t[threadIdx.x][i]);
}

// ---------------- fp16 tensor-core GEMM --------------------------------------
// z = 0..7 : g_hxh[z] = fp16( x @ W[z] )
// z = 8    : out      = h_bias + sqrt(0.5) * (x @ loop_W)   (fp32)
#define GBM 128
#define GBN 128
#define GBK 32
#define PITCH 40   // halfs per smem row (80 B) -> conflict-free ldmatrix

__device__ __forceinline__ void cp16(void* dst, const void* src) {
    unsigned s = (unsigned)__cvta_generic_to_shared(dst);
    asm volatile("cp.async.cg.shared.global [%0],[%1],16;" :: "r"(s), "l"(src));
}
__device__ __forceinline__ void cp_commit() { asm volatile("cp.async.commit_group;"); }
template<int N> __device__ __forceinline__ void cp_wait() {
    asm volatile("cp.async.wait_group %0;" :: "n"(N));
}
__device__ __forceinline__ void ldm_x4(unsigned r[4], const void* p) {
    unsigned a = (unsigned)__cvta_generic_to_shared(p);
    asm volatile("ldmatrix.sync.aligned.m8n8.x4.shared.b16 {%0,%1,%2,%3},[%4];"
                 : "=r"(r[0]), "=r"(r[1]), "=r"(r[2]), "=r"(r[3]) : "r"(a));
}
__device__ __forceinline__ void mma_f16(float c[4], const unsigned a[4], const unsigned b[2]) {
    asm volatile(
        "mma.sync.aligned.m16n8k16.row.col.f32.f16.f16.f32 "
        "{%0,%1,%2,%3},{%4,%5,%6,%7},{%8,%9},{%0,%1,%2,%3};"
        : "+f"(c[0]), "+f"(c[1]), "+f"(c[2]), "+f"(c[3])
        : "r"(a[0]), "r"(a[1]), "r"(a[2]), "r"(a[3]), "r"(b[0]), "r"(b[1]));
}

__global__ __launch_bounds__(256) void k_gemm_f16(
    const float* __restrict__ h_bias, float* __restrict__ out)
{
    __shared__ __half As[2][GBM * PITCH];
    __shared__ __half Bs[2][GBN * PITCH];

    const int r  = blockIdx.z;
    const int m0 = blockIdx.x * GBM;
    const int n0 = blockIdx.y * GBN;
    const __half* Bg = g_wt + ((size_t)r << 16);

    const int tid  = threadIdx.x;
    const int lane = tid & 31;
    const int warp = tid >> 5;
    const int wm   = warp & 3;    // 4 warps in m: 32 rows each
    const int wn   = warp >> 2;   // 2 warps in n: 64 cols each

    float c[2][8][4];
    #pragma unroll
    for (int i = 0; i < 2; i++)
        #pragma unroll
        for (int j = 0; j < 8; j++)
            #pragma unroll
            for (int q = 0; q < 4; q++) c[i][j][q] = 0.f;

    // loader mapping: idx -> (row = idx>>2, 16B segment = idx&3)
    auto load_stage = [&](int st, int k0) {
        #pragma unroll
        for (int j = 0; j < 2; j++) {
            int idx = tid + j * 256;
            int row = idx >> 2, seg = idx & 3;
            int gm = m0 + row;
            if (gm < N_NODES)
                cp16(&As[st][row * PITCH + seg * 8],
                     g_xh + (size_t)gm * FEAT + k0 + seg * 8);
            cp16(&Bs[st][row * PITCH + seg * 8],
                 Bg + (size_t)(n0 + row) * FEAT + k0 + seg * 8);
        }
    };

    load_stage(0, 0);
    cp_commit();

    const int NSTAGES = FEAT / GBK;  // 8
    for (int it = 0; it < NSTAGES; it++) {
        int st = it & 1;
        if (it + 1 < NSTAGES) { load_stage(st ^ 1, (it + 1) * GBK); cp_commit(); }
        if (it + 1 < NSTAGES) cp_wait<1>(); else cp_wait<0>();
        __syncthreads();

        #pragma unroll
        for (int ks = 0; ks < 2; ks++) {
            const int kb = ks * 16;
            unsigned a[2][4];
            #pragma unroll
            for (int mf = 0; mf < 2; mf++) {
                int mrow = wm * 32 + mf * 16 + (lane & 15);
                ldm_x4(a[mf], &As[st][mrow * PITCH + kb + ((lane >> 4) << 3)]);
            }
            unsigned b[8][2];
            #pragma unroll
            for (int nb = 0; nb < 4; nb++) {
                int nrow = wn * 64 + nb * 16 + (lane & 7) + ((lane >> 4) << 3);
                unsigned t[4];
                ldm_x4(t, &Bs[st][nrow * PITCH + kb + (((lane >> 3) & 1) << 3)]);
                b[2 * nb][0] = t[0]; b[2 * nb][1] = t[1];
                b[2 * nb + 1][0] = t[2]; b[2 * nb + 1][1] = t[3];
            }
            #pragma unroll
            for (int mf = 0; mf < 2; mf++)
                #pragma unroll
                for (int nf = 0; nf < 8; nf++)
                    mma_f16(c[mf][nf], a[mf], b[nf]);
        }
        __syncthreads();
    }

    // epilogue
    #pragma unroll
    for (int mf = 0; mf < 2; mf++) {
        int row0 = m0 + wm * 32 + mf * 16 + (lane >> 2);   // rows row0, row0+8
        #pragma unroll
        for (int nf = 0; nf < 8; nf++) {
            int col = n0 + wn * 64 + nf * 8 + (lane & 3) * 2;
            if (r < N_RELS) {
                if (row0 < N_NODES)
                    *(__half2*)(g_hxh + (((size_t)r * N_NODES + row0) << 8) + col) =
                        __floats2half2_rn(c[mf][nf][0], c[mf][nf][1]);
                if (row0 + 8 < N_NODES)
                    *(__half2*)(g_hxh + (((size_t)r * N_NODES + row0 + 8) << 8) + col) =
                        __floats2half2_rn(c[mf][nf][2], c[mf][nf][3]);
            } else {
                float2 bv = *(const float2*)(h_bias + col);
                if (row0 < N_NODES)
                    *(float2*)(out + ((size_t)row0 << 8) + col) =
                        make_float2(bv.x + SQRT_HALF * c[mf][nf][0],
                                    bv.y + SQRT_HALF * c[mf][nf][1]);
                if (row0 + 8 < N_NODES)
                    *(float2*)(out + ((size_t)(row0 + 8) << 8) + col) =
                        make_float2(bv.x + SQRT_HALF * c[mf][nf][2],
                                    bv.y + SQRT_HALF * c[mf][nf][3]);
            }
        }
    }
}

// ---------------- aggregation: 1 warp / node, fp16 gather --------------------
__global__ __launch_bounds__(256) void k_agg(float* __restrict__ out) {
    int node = blockIdx.x * blockDim.y + threadIdx.y;
    if (node >= N_NODES) return;
    int lane = threadIdx.x;
    int beg = g_offsets[node];
    int end = g_offsets[node + 1];

    float acc[8];
    #pragma unroll
    for (int j = 0; j < 8; j++) acc[j] = 0.f;

    for (int i = beg; i < end; i++) {
        unsigned p = g_sorted[i];
        unsigned src = p & 0xFFFFFu;
        unsigned rel = p >> 20;
        const uint4* row = (const uint4*)(g_hxh + (((size_t)rel * N_NODES + src) << 8));
        uint4 v = __ldg(row + lane);   // 8 halfs = cols [8*lane, 8*lane+8)
        __half2 h0 = *reinterpret_cast<const __half2*>(&v.x);
        __half2 h1 = *reinterpret_cast<const __half2*>(&v.y);
        __half2 h2 = *reinterpret_cast<const __half2*>(&v.z);
        __half2 h3 = *reinterpret_cast<const __half2*>(&v.w);
        float2 f0 = __half22float2(h0), f1 = __half22float2(h1);
        float2 f2 = __half22float2(h2), f3 = __half22float2(h3);
        acc[0] += f0.x; acc[1] += f0.y; acc[2] += f1.x; acc[3] += f1.y;
        acc[4] += f2.x; acc[5] += f2.y; acc[6] += f3.x; acc[7] += f3.y;
    }

    float4* o = (float4*)(out + ((size_t)node << 8)) + lane * 2;
    float4 c0 = o[0], c1 = o[1];
    c0.x += SQRT_HALF * acc[0]; c0.y += SQRT_HALF * acc[1];
    c0.z += SQRT_HALF * acc[2]; c0.w += SQRT_HALF * acc[3];
    c1.x += SQRT_HALF * acc[4]; c1.y += SQRT_HALF * acc[5];
    c1.z += SQRT_HALF * acc[6]; c1.w += SQRT_HALF * acc[7];
    o[0] = c0; o[1] = c1;
}

// ---------------- launch -----------------------------------------------------
extern "C" void kernel_launch(void* const* d_in, const int* in_sizes, int n_in,
                              void* d_out, int out_size) {
    const int*   edge_index  = (const int*)d_in[0];
    const float* x           = (const float*)d_in[1];
    const int*   edge_type   = (const int*)d_in[2];
    const float* weight      = (const float*)d_in[3];
    const float* h_bias      = (const float*)d_in[4];
    const float* loop_weight = (const float*)d_in[5];
    float* out = (float*)d_out;

    // converts (independent of sort)
    k_convert_x<<<(N_NODES * FEAT / 2 + 255) / 256, 256>>>(x);
    {
        dim3 b(32, 8), g(FEAT / 32, FEAT / 32, N_RELS + 1);
        k_convert_w<<<g, b>>>(weight, loop_weight);
    }

    // sort pipeline
    k_zero_counts<<<(N_NODES + 255) / 256, 256>>>();
    k_hist<<<(N_EDGES + 255) / 256, 256>>>(edge_index);
    k_scan<<<1, 1024>>>();
    k_scatter<<<(N_EDGES + 255) / 256, 256>>>(edge_index, edge_type);

    // fp16 tensor-core GEMM: 8 relations + self-loop
    dim3 gg((N_NODES + GBM - 1) / GBM, FEAT / GBN, N_RELS + 1);
    k_gemm_f16<<<gg, 256>>>(h_bias, out);

    // per-node aggregation
    dim3 bb(32, 8);
    k_agg<<<(N_NODES + 7) / 8, bb>>>(out);
}

// round 7
// speedup vs baseline: 4.0705x; 1.1557x over previous
#include <cuda_runtime.h>
#include <cuda_fp16.h>
#include <cstdint>

#define N_NODES 50000
#define N_EDGES 800000
#define FEAT    256
#define N_RELS  8
#define KTOT    2304              // (N_RELS+1) * FEAT
#define N_BUCK  (N_NODES * N_RELS)   // 400000
#define SQRT_HALF 0.70710678118654752f

// ---------------- scratch ----------------------------------------------------
__device__ __half g_A[(size_t)N_NODES * KTOT];        // 230.4 MB: [aggx_0..7 | x]
__device__ __half g_xh[(size_t)N_NODES * FEAT];       // 25.6 MB (L2-resident gather src)
__device__ __half g_wt2[(size_t)FEAT * KTOT];         // 1.18 MB: [n][k] = W^T * sqrt(1/2)
__device__ int      g_counts[N_BUCK];
__device__ int      g_offsets[N_BUCK + 1];
__device__ int      g_cursor[N_BUCK];
__device__ int      g_blocksum[400];
__device__ int      g_blockpre[400];
__device__ unsigned g_sorted[N_EDGES];                // src node id

#define SCAN_NB ((N_BUCK + 1023) / 1024)   // 391

// ---------------- sort pipeline: key = dst*8 + rel ---------------------------
__global__ void k_zero_counts() {
    int i = blockIdx.x * blockDim.x + threadIdx.x;
    if (i < N_BUCK) g_counts[i] = 0;
}

__global__ void k_hist(const int* __restrict__ edge_index,
                       const int* __restrict__ edge_type) {
    int e = blockIdx.x * blockDim.x + threadIdx.x;
    if (e < N_EDGES) {
        int d = edge_index[N_EDGES + e];
        int r = edge_type[e];
        if (d >= 0 && d < N_NODES)
            atomicAdd(&g_counts[d * N_RELS + r], 1);
    }
}

// pass 1: per-block sums
__global__ void k_scan1() {
    __shared__ int s[1024];
    int idx = blockIdx.x * 1024 + threadIdx.x;
    int v = (idx < N_BUCK) ? g_counts[idx] : 0;
    s[threadIdx.x] = v;
    __syncthreads();
    for (int off = 512; off > 0; off >>= 1) {
        if (threadIdx.x < off) s[threadIdx.x] += s[threadIdx.x + off];
        __syncthreads();
    }
    if (threadIdx.x == 0) g_blocksum[blockIdx.x] = s[0];
}

// pass 2: exclusive scan of block sums (single block)
__global__ void k_scan2() {
    __shared__ int s[512];
    int t = threadIdx.x;
    int v = (t < SCAN_NB) ? g_blocksum[t] : 0;
    s[t] = v;
    __syncthreads();
    int val = v;
    for (int off = 1; off < 512; off <<= 1) {
        int u = (t >= off) ? s[t - off] : 0;
        __syncthreads();
        val += u;
        s[t] = val;
        __syncthreads();
    }
    if (t < SCAN_NB) g_blockpre[t] = val - v;   // exclusive
    if (t == 0) g_offsets[N_BUCK] = N_EDGES;
}

// pass 3: block-local exclusive scan + add block prefix
__global__ void k_scan3() {
    __shared__ int s[1024];
    int idx = blockIdx.x * 1024 + threadIdx.x;
    int t = threadIdx.x;
    int v = (idx < N_BUCK) ? g_counts[idx] : 0;
    s[t] = v;
    __syncthreads();
    int val = v;
    for (int off = 1; off < 1024; off <<= 1) {
        int u = (t >= off) ? s[t - off] : 0;
        __syncthreads();
        val += u;
        s[t] = val;
        __syncthreads();
    }
    if (idx < N_BUCK) {
        int o = g_blockpre[blockIdx.x] + val - v;
        g_offsets[idx] = o;
        g_cursor[idx]  = o;
    }
}

__global__ void k_scatter(const int* __restrict__ edge_index,
                          const int* __restrict__ edge_type) {
    int e = blockIdx.x * blockDim.x + threadIdx.x;
    if (e < N_EDGES) {
        int srcv = edge_index[e];
        int d    = edge_index[N_EDGES + e];
        int r    = edge_type[e];
        if (d >= 0 && d < N_NODES) {
            int pos = atomicAdd(&g_cursor[d * N_RELS + r], 1);
            g_sorted[pos] = (unsigned)srcv;
        }
    }
}

// ---------------- converts ---------------------------------------------------
// x fp32 -> g_xh (compact) and A block 8
__global__ void k_convert_x(const float* __restrict__ x) {
    int i = blockIdx.x * blockDim.x + threadIdx.x;   // half2 index
    const int total = N_NODES * FEAT / 2;
    if (i < total) {
        float2 v = *((const float2*)x + i);
        __half2 h = __floats2half2_rn(v.x, v.y);
        *((__half2*)g_xh + i) = h;
        int d = i >> 7, j = i & 127;                 // 128 half2 per row
        *((__half2*)g_A + (size_t)d * (KTOT / 2) + (N_RELS * FEAT / 2) + j) = h;
    }
}

// W[r][k][n] fp32 -> g_wt2[n][r*256+k] fp16 * sqrt(0.5)  (transpose)
__global__ void k_convert_w(const float* __restrict__ W, const float* __restrict__ LW) {
    int r = blockIdx.z;
    const float* src = (r < N_RELS) ? (W + (size_t)r * FEAT * FEAT) : LW;
    int k0 = blockIdx.x * 32, n0 = blockIdx.y * 32;
    __shared__ float t[32][33];
    for (int i = threadIdx.y; i < 32; i += 8)
        t[i][threadIdx.x] = src[(size_t)(k0 + i) * FEAT + n0 + threadIdx.x];
    __syncthreads();
    for (int i = threadIdx.y; i < 32; i += 8)
        g_wt2[(size_t)(n0 + i) * KTOT + r * FEAT + k0 + threadIdx.x] =
            __float2half(t[threadIdx.x][i] * SQRT_HALF);
}

// ---------------- edge aggregation: 1 warp per (dst,rel) bucket --------------
// A[d][r*256 .. r*256+255] = fp16( sum_{e in bucket} x_h[src_e] )
__global__ __launch_bounds__(256) void k_agg_gather() {
    int p = blockIdx.x * 8 + threadIdx.y;
    if (p >= N_BUCK) return;
    int lane = threadIdx.x;
    int d = p >> 3, r = p & 7;
    int beg = g_offsets[p];
    int end = g_offsets[p + 1];

    float acc[8];
    #pragma unroll
    for (int j = 0; j < 8; j++) acc[j] = 0.f;

    for (int i = beg; i < end; i++) {
        unsigned srcv = g_sorted[i];
        const uint4* row = (const uint4*)(g_xh + ((size_t)srcv << 8));
        uint4 v = __ldg(row + lane);   // 8 halfs
        float2 f0 = __half22float2(*reinterpret_cast<const __half2*>(&v.x));
        float2 f1 = __half22float2(*reinterpret_cast<const __half2*>(&v.y));
        float2 f2 = __half22float2(*reinterpret_cast<const __half2*>(&v.z));
        float2 f3 = __half22float2(*reinterpret_cast<const __half2*>(&v.w));
        acc[0] += f0.x; acc[1] += f0.y; acc[2] += f1.x; acc[3] += f1.y;
        acc[4] += f2.x; acc[5] += f2.y; acc[6] += f3.x; acc[7] += f3.y;
    }

    __half2 h0 = __floats2half2_rn(acc[0], acc[1]);
    __half2 h1 = __floats2half2_rn(acc[2], acc[3]);
    __half2 h2 = __floats2half2_rn(acc[4], acc[5]);
    __half2 h3 = __floats2half2_rn(acc[6], acc[7]);
    uint4 o;
    o.x = *reinterpret_cast<unsigned*>(&h0);
    o.y = *reinterpret_cast<unsigned*>(&h1);
    o.z = *reinterpret_cast<unsigned*>(&h2);
    o.w = *reinterpret_cast<unsigned*>(&h3);
    *(uint4*)(g_A + (size_t)d * KTOT + r * FEAT + lane * 8) = o;
}

// ---------------- fp16 tensor-core GEMM: out = A @ Wt2 + bias ----------------
#define GBM 128
#define GBN 128
#define GBK 32
#define PITCH 40

__device__ __forceinline__ void cp16(void* dst, const void* src) {
    unsigned s = (unsigned)__cvta_generic_to_shared(dst);
    asm volatile("cp.async.cg.shared.global [%0],[%1],16;" :: "r"(s), "l"(src));
}
__device__ __forceinline__ void cp_commit() { asm volatile("cp.async.commit_group;"); }
template<int N> __device__ __forceinline__ void cp_wait() {
    asm volatile("cp.async.wait_group %0;" :: "n"(N));
}
__device__ __forceinline__ void ldm_x4(unsigned r[4], const void* p) {
    unsigned a = (unsigned)__cvta_generic_to_shared(p);
    asm volatile("ldmatrix.sync.aligned.m8n8.x4.shared.b16 {%0,%1,%2,%3},[%4];"
                 : "=r"(r[0]), "=r"(r[1]), "=r"(r[2]), "=r"(r[3]) : "r"(a));
}
__device__ __forceinline__ void mma_f16(float c[4], const unsigned a[4], const unsigned b[2]) {
    asm volatile(
        "mma.sync.aligned.m16n8k16.row.col.f32.f16.f16.f32 "
        "{%0,%1,%2,%3},{%4,%5,%6,%7},{%8,%9},{%0,%1,%2,%3};"
        : "+f"(c[0]), "+f"(c[1]), "+f"(c[2]), "+f"(c[3])
        : "r"(a[0]), "r"(a[1]), "r"(a[2]), "r"(a[3]), "r"(b[0]), "r"(b[1]));
}

__global__ __launch_bounds__(256) void k_gemm_f16(
    const float* __restrict__ h_bias, float* __restrict__ out)
{
    __shared__ __half As[2][GBM * PITCH];
    __shared__ __half Bs[2][GBN * PITCH];

    const int m0 = blockIdx.x * GBM;
    const int n0 = blockIdx.y * GBN;

    const int tid  = threadIdx.x;
    const int lane = tid & 31;
    const int warp = tid >> 5;
    const int wm   = warp & 3;    // 4 warps in m
    const int wn   = warp >> 2;   // 2 warps in n

    float c[2][8][4];
    #pragma unroll
    for (int i = 0; i < 2; i++)
        #pragma unroll
        for (int j = 0; j < 8; j++)
            #pragma unroll
            for (int q = 0; q < 4; q++) c[i][j][q] = 0.f;

    auto load_stage = [&](int st, int k0) {
        #pragma unroll
        for (int j = 0; j < 2; j++) {
            int idx = tid + j * 256;
            int row = idx >> 2, seg = idx & 3;
            int gm = m0 + row;
            if (gm < N_NODES)
                cp16(&As[st][row * PITCH + seg * 8],
                     g_A + (size_t)gm * KTOT + k0 + seg * 8);
            cp16(&Bs[st][row * PITCH + seg * 8],
                 g_wt2 + (size_t)(n0 + row) * KTOT + k0 + seg * 8);
        }
    };

    load_stage(0, 0);
    cp_commit();

    const int NSTAGES = KTOT / GBK;  // 72
    for (int it = 0; it < NSTAGES; it++) {
        int st = it & 1;
        if (it + 1 < NSTAGES) { load_stage(st ^ 1, (it + 1) * GBK); cp_commit(); }
        if (it + 1 < NSTAGES) cp_wait<1>(); else cp_wait<0>();
        __syncthreads();

        #pragma unroll
        for (int ks = 0; ks < 2; ks++) {
            const int kb = ks * 16;
            unsigned a[2][4];
            #pragma unroll
            for (int mf = 0; mf < 2; mf++) {
                int mrow = wm * 32 + mf * 16 + (lane & 15);
                ldm_x4(a[mf], &As[st][mrow * PITCH + kb + ((lane >> 4) << 3)]);
            }
            unsigned b[8][2];
            #pragma unroll
            for (int nb = 0; nb < 4; nb++) {
                int nrow = wn * 64 + nb * 16 + (lane & 7) + ((lane >> 4) << 3);
                unsigned t[4];
                ldm_x4(t, &Bs[st][nrow * PITCH + kb + (((lane >> 3) & 1) << 3)]);
                b[2 * nb][0] = t[0]; b[2 * nb][1] = t[1];
                b[2 * nb + 1][0] = t[2]; b[2 * nb + 1][1] = t[3];
            }
            #pragma unroll
            for (int mf = 0; mf < 2; mf++)
                #pragma unroll
                for (int nf = 0; nf < 8; nf++)
                    mma_f16(c[mf][nf], a[mf], b[nf]);
        }
        __syncthreads();
    }

    // epilogue: out = C + bias
    #pragma unroll
    for (int mf = 0; mf < 2; mf++) {
        int row0 = m0 + wm * 32 + mf * 16 + (lane >> 2);
        #pragma unroll
        for (int nf = 0; nf < 8; nf++) {
            int col = n0 + wn * 64 + nf * 8 + (lane & 3) * 2;
            float2 bv = *(const float2*)(h_bias + col);
            if (row0 < N_NODES)
                *(float2*)(out + ((size_t)row0 << 8) + col) =
                    make_float2(bv.x + c[mf][nf][0], bv.y + c[mf][nf][1]);
            if (row0 + 8 < N_NODES)
                *(float2*)(out + ((size_t)(row0 + 8) << 8) + col) =
                    make_float2(bv.x + c[mf][nf][2], bv.y + c[mf][nf][3]);
        }
    }
}

// ---------------- launch -----------------------------------------------------
extern "C" void kernel_launch(void* const* d_in, const int* in_sizes, int n_in,
                              void* d_out, int out_size) {
    const int*   edge_index  = (const int*)d_in[0];
    const float* x           = (const float*)d_in[1];
    const int*   edge_type   = (const int*)d_in[2];
    const float* weight      = (const float*)d_in[3];
    const float* h_bias      = (const float*)d_in[4];
    const float* loop_weight = (const float*)d_in[5];
    float* out = (float*)d_out;

    // converts
    k_convert_x<<<(N_NODES * FEAT / 2 + 255) / 256, 256>>>(x);
    {
        dim3 b(32, 8), g(FEAT / 32, FEAT / 32, N_RELS + 1);
        k_convert_w<<<g, b>>>(weight, loop_weight);
    }

    // sort pipeline over (dst, rel) buckets
    k_zero_counts<<<(N_BUCK + 255) / 256, 256>>>();
    k_hist<<<(N_EDGES + 255) / 256, 256>>>(edge_index, edge_type);
    k_scan1<<<SCAN_NB, 1024>>>();
    k_scan2<<<1, 512>>>();
    k_scan3<<<SCAN_NB, 1024>>>();
    k_scatter<<<(N_EDGES + 255) / 256, 256>>>(edge_index, edge_type);

    // edge aggregation into A (L2-resident gather of x_h)
    {
        dim3 b(32, 8);
        k_agg_gather<<<(N_BUCK + 7) / 8, b>>>();
    }

    // single fused GEMM: out = A @ Wt2 + bias
    dim3 gg((N_NODES + GBM - 1) / GBM, FEAT / GBN);
    k_gemm_f16<<<gg, 256>>>(h_bias, out);
}